// round 1
// baseline (speedup 1.0000x reference)
#include <cuda_runtime.h>
#include <math_constants.h>

#define NN    10000
#define EE    160000
#define ET    170000   // EE + NN self loops
#define SNAP  16       // B*T
#define TT    8
#define BB    2
#define CIN   64
#define CC    32

// ---------------- static device scratch ----------------
__device__ float g_xl[SNAP * NN * CC];       // 20.5 MB  [s][n][c]
__device__ float g_xr[SNAP * NN * CC];       // 20.5 MB
__device__ float g_ee[ET * CC];              // 21.8 MB  [edge][c]
__device__ float g_gath[BB * NN * TT * CC];  // 20.5 MB  [b][n][t][c]
__device__ float g_loop_sum[NN * 3];
__device__ float g_loop_cnt[NN];
__device__ int   g_indeg[NN];
__device__ int   g_cursor[NN];
__device__ int   g_csr_off[NN + 1];
__device__ int   g_csr_src[ET];
__device__ int   g_csr_eid[ET];

// ---------------- kernels ----------------

__global__ void k_zero() {
    int i = blockIdx.x * blockDim.x + threadIdx.x;
    if (i < NN) {
        g_loop_cnt[i] = 0.f;
        g_indeg[i] = 0;
        g_cursor[i] = 0;
        g_loop_sum[i * 3 + 0] = 0.f;
        g_loop_sum[i * 3 + 1] = 0.f;
        g_loop_sum[i * 3 + 2] = 0.f;
    }
}

__global__ void k_deg(const int* __restrict__ ei, const float* __restrict__ ea) {
    int e = blockIdx.x * blockDim.x + threadIdx.x;
    if (e >= EE) return;
    int dst = ei[EE + e];
    atomicAdd(&g_loop_sum[dst * 3 + 0], ea[e * 3 + 0]);
    atomicAdd(&g_loop_sum[dst * 3 + 1], ea[e * 3 + 1]);
    atomicAdd(&g_loop_sum[dst * 3 + 2], ea[e * 3 + 2]);
    atomicAdd(&g_loop_cnt[dst], 1.f);
    atomicAdd(&g_indeg[dst], 1);
}

// single-block exclusive scan of (indeg[n] + 1) -> csr_off
__global__ void k_scan() {
    __shared__ int sh[1024];
    __shared__ int sbase;
    int tid = threadIdx.x;
    if (tid == 0) sbase = 0;
    __syncthreads();
    for (int start = 0; start < NN; start += 1024) {
        int i = start + tid;
        int v = (i < NN) ? (g_indeg[i] + 1) : 0;
        sh[tid] = v;
        __syncthreads();
        for (int off = 1; off < 1024; off <<= 1) {
            int t = 0;
            if (tid >= off) t = sh[tid - off];
            __syncthreads();
            sh[tid] += t;
            __syncthreads();
        }
        if (i < NN) g_csr_off[i] = sbase + sh[tid] - v;
        int tot = sh[1023];
        __syncthreads();
        if (tid == 0) sbase += tot;
        __syncthreads();
    }
    if (tid == 0) g_csr_off[NN] = sbase;
}

__global__ void k_scatter(const int* __restrict__ ei) {
    int e = blockIdx.x * blockDim.x + threadIdx.x;
    if (e < EE) {
        int src = ei[e];
        int dst = ei[EE + e];
        int pos = g_csr_off[dst] + atomicAdd(&g_cursor[dst], 1);
        g_csr_src[pos] = src;
        g_csr_eid[pos] = e;
    } else if (e < EE + NN) {
        int n = e - EE;
        int pos = g_csr_off[n + 1] - 1;  // self-loop sits in the last slot
        g_csr_src[pos] = n;
        g_csr_eid[pos] = EE + n;
    }
}

// ee[r][c] = attr_r @ W_e  (self-loop rows use segment mean of incoming attr)
__global__ void k_ee(const float* __restrict__ edge_attr, const float* __restrict__ W_e) {
    int idx = blockIdx.x * blockDim.x + threadIdx.x;
    int r = idx >> 5, c = idx & 31;
    if (r >= ET) return;
    float a0, a1, a2;
    if (r < EE) {
        a0 = edge_attr[r * 3 + 0];
        a1 = edge_attr[r * 3 + 1];
        a2 = edge_attr[r * 3 + 2];
    } else {
        int n = r - EE;
        float cnt = fmaxf(g_loop_cnt[n], 1.f);
        float inv = 1.f / cnt;
        a0 = g_loop_sum[n * 3 + 0] * inv;
        a1 = g_loop_sum[n * 3 + 1] * inv;
        a2 = g_loop_sum[n * 3 + 2] * inv;
    }
    g_ee[r * 32 + c] = a0 * W_e[c] + a1 * W_e[32 + c] + a2 * W_e[64 + c];
}

// xl = x@W_l + b_l ; xr = x@W_r + b_r  (warp per row, 8 rows/block)
__global__ void k_xlr(const float* __restrict__ x,
                      const float* __restrict__ W_l, const float* __restrict__ b_l,
                      const float* __restrict__ W_r, const float* __restrict__ b_r) {
    __shared__ float sWl[CIN * CC];
    __shared__ float sWr[CIN * CC];
    __shared__ float sx[8][CIN];
    int tid = threadIdx.x;
    for (int i = tid; i < CIN * CC; i += 256) {
        sWl[i] = W_l[i];
        sWr[i] = W_r[i];
    }
    __syncthreads();
    int w = tid >> 5, lane = tid & 31;
    int row = blockIdx.x * 8 + w;
    if (row >= SNAP * NN) return;
    const float* xp = x + (long)row * CIN;
    sx[w][lane] = xp[lane];
    sx[w][lane + 32] = xp[lane + 32];
    __syncwarp();
    float al = 0.f, ar = 0.f;
#pragma unroll
    for (int k = 0; k < CIN; k++) {
        float xv = sx[w][k];
        al += xv * sWl[k * 32 + lane];
        ar += xv * sWr[k * 32 + lane];
    }
    g_xl[row * 32 + lane] = al + b_l[lane];
    g_xr[row * 32 + lane] = ar + b_r[lane];
}

// GATv2 with online softmax: warp per (snapshot s, node n); lane = channel
__global__ void k_gat(const float* __restrict__ att, const float* __restrict__ bias_gat) {
    int n = blockIdx.x * 8 + (threadIdx.x >> 5);
    int s = blockIdx.y;
    if (n >= NN) return;
    int c = threadIdx.x & 31;

    float xr_c = g_xr[(s * NN + n) * 32 + c];
    float attc = att[c];
    int off = g_csr_off[n], end = g_csr_off[n + 1];

    float m = -CUDART_INF_F, ssum = 0.f, acc = 0.f;
    for (int j = off; j < end; j++) {
        int srcj = g_csr_src[j];
        int eid  = g_csr_eid[j];
        float xlv = g_xl[(s * NN + srcj) * 32 + c];
        float v = xlv + xr_c + g_ee[eid * 32 + c];
        v = (v > 0.f) ? v : 0.2f * v;      // leaky_relu(0.2)
        float ev = v * attc;
#pragma unroll
        for (int o = 16; o > 0; o >>= 1)
            ev += __shfl_xor_sync(0xffffffffu, ev, o);
        float mn = fmaxf(m, ev);
        float sc = __expf(m - mn);         // exp(-inf)=0 handles first edge
        float wv = __expf(ev - mn);
        ssum = ssum * sc + wv;
        acc  = acc * sc + wv * xlv;
        m = mn;
    }
    int b = s >> 3, t = s & 7;
    g_gath[((b * NN + n) * TT + t) * 32 + c] = acc / ssum + bias_gat[c];
}

// GRU: warp per (b,n) sequence; lane = channel
__global__ void k_gru(const float* __restrict__ W_ih, const float* __restrict__ W_hh,
                      const float* __restrict__ b_ih, const float* __restrict__ b_hh,
                      float* __restrict__ out) {
    __shared__ float sWi[32 * 96];  // transposed: [h][g*32+c]
    __shared__ float sWh[32 * 96];
    __shared__ float sbi[96], sbh[96];
    int tid = threadIdx.x;
    for (int i = tid; i < 96 * 32; i += 256) {
        int row = i >> 5, h = i & 31;  // global layout W[row][h], row = g*32+c
        sWi[h * 96 + row] = W_ih[i];
        sWh[h * 96 + row] = W_hh[i];
    }
    for (int i = tid; i < 96; i += 256) {
        sbi[i] = b_ih[i];
        sbh[i] = b_hh[i];
    }
    __syncthreads();

    int m = blockIdx.x * 8 + (tid >> 5);
    if (m >= BB * NN) return;
    int c = tid & 31;
    int b = m / NN, n = m - b * NN;

    float bi0 = sbi[c], bi1 = sbi[32 + c], bi2 = sbi[64 + c];
    float bh0 = sbh[c], bh1 = sbh[32 + c], bh2 = sbh[64 + c];

    float h = 0.f;
    for (int t = 0; t < TT; t++) {
        float xc = g_gath[(m * TT + t) * 32 + c];
        float ir = bi0, iz = bi1, inn = bi2;
        float hr = bh0, hz = bh1, hn = bh2;
#pragma unroll
        for (int hh = 0; hh < 32; hh++) {
            float xv = __shfl_sync(0xffffffffu, xc, hh);
            float hv = __shfl_sync(0xffffffffu, h, hh);
            const float* wi = &sWi[hh * 96];
            const float* wh = &sWh[hh * 96];
            ir  += xv * wi[c];
            iz  += xv * wi[32 + c];
            inn += xv * wi[64 + c];
            hr  += hv * wh[c];
            hz  += hv * wh[32 + c];
            hn  += hv * wh[64 + c];
        }
        float r = 1.f / (1.f + __expf(-(ir + hr)));
        float z = 1.f / (1.f + __expf(-(iz + hz)));
        float pre = inn + r * hn;
        float e2 = __expf(-2.f * pre);
        float nn_ = 2.f / (1.f + e2) - 1.f;   // tanh, NaN-safe at both infinities
        h = (1.f - z) * nn_ + z * h;
        out[((long)(b * TT + t) * NN + n) * 32 + c] = h;
    }
}

// ---------------- launch ----------------
extern "C" void kernel_launch(void* const* d_in, const int* in_sizes, int n_in,
                              void* d_out, int out_size) {
    const float* x        = (const float*)d_in[0];
    const int*   ei       = (const int*)d_in[1];
    const float* eattr    = (const float*)d_in[2];
    const float* W_l      = (const float*)d_in[3];
    const float* b_l      = (const float*)d_in[4];
    const float* W_r      = (const float*)d_in[5];
    const float* b_r      = (const float*)d_in[6];
    const float* W_e      = (const float*)d_in[7];
    const float* att      = (const float*)d_in[8];
    const float* bias_gat = (const float*)d_in[9];
    const float* W_ih     = (const float*)d_in[10];
    const float* W_hh     = (const float*)d_in[11];
    const float* b_ih     = (const float*)d_in[12];
    const float* b_hh     = (const float*)d_in[13];
    float* out = (float*)d_out;

    k_zero<<<(NN + 255) / 256, 256>>>();
    k_deg<<<(EE + 255) / 256, 256>>>(ei, eattr);
    k_scan<<<1, 1024>>>();
    k_scatter<<<(EE + NN + 255) / 256, 256>>>(ei);
    k_ee<<<(ET * 32 + 255) / 256, 256>>>(eattr, W_e);
    k_xlr<<<(SNAP * NN + 7) / 8, 256>>>(x, W_l, b_l, W_r, b_r);
    dim3 ggat((NN + 7) / 8, SNAP);
    k_gat<<<ggat, 256>>>(att, bias_gat);
    k_gru<<<(BB * NN + 7) / 8, 256>>>(W_ih, W_hh, b_ih, b_hh, out);
}

// round 2
// speedup vs baseline: 1.0579x; 1.0579x over previous
#include <cuda_runtime.h>
#include <math_constants.h>

#define NN    10000
#define EE    160000
#define ET    170000   // EE + NN self loops
#define SNAP  16       // B*T
#define TT    8
#define BB    2
#define CIN   64
#define CC    32

// ---------------- static device scratch ----------------
__device__ float g_xl[NN * SNAP * CC];       // [n][s][c]
__device__ float g_xr[NN * SNAP * CC];       // [n][s][c]
__device__ float g_ee[ET * CC];              // [edge][c]
__device__ float g_gath[BB * NN * TT * CC];  // [b][n][t][c]
__device__ float g_loop_sum[NN * 3];
__device__ float g_loop_cnt[NN];
__device__ int   g_indeg[NN];
__device__ int   g_cursor[NN];
__device__ int   g_csr_off[NN + 1];
__device__ int   g_csr_src[ET];
__device__ int   g_csr_eid[ET];

// ---------------- kernels ----------------

__global__ void k_zero() {
    int i = blockIdx.x * blockDim.x + threadIdx.x;
    if (i < NN) {
        g_loop_cnt[i] = 0.f;
        g_indeg[i] = 0;
        g_cursor[i] = 0;
        g_loop_sum[i * 3 + 0] = 0.f;
        g_loop_sum[i * 3 + 1] = 0.f;
        g_loop_sum[i * 3 + 2] = 0.f;
    }
}

__global__ void k_deg(const int* __restrict__ ei, const float* __restrict__ ea) {
    int e = blockIdx.x * blockDim.x + threadIdx.x;
    if (e >= EE) return;
    int dst = ei[EE + e];
    atomicAdd(&g_loop_sum[dst * 3 + 0], ea[e * 3 + 0]);
    atomicAdd(&g_loop_sum[dst * 3 + 1], ea[e * 3 + 1]);
    atomicAdd(&g_loop_sum[dst * 3 + 2], ea[e * 3 + 2]);
    atomicAdd(&g_loop_cnt[dst], 1.f);
    atomicAdd(&g_indeg[dst], 1);
}

// single-block exclusive scan of (indeg[n] + 1) -> csr_off
__global__ void k_scan() {
    __shared__ int sh[1024];
    __shared__ int sbase;
    int tid = threadIdx.x;
    if (tid == 0) sbase = 0;
    __syncthreads();
    for (int start = 0; start < NN; start += 1024) {
        int i = start + tid;
        int v = (i < NN) ? (g_indeg[i] + 1) : 0;
        sh[tid] = v;
        __syncthreads();
        for (int off = 1; off < 1024; off <<= 1) {
            int t = 0;
            if (tid >= off) t = sh[tid - off];
            __syncthreads();
            sh[tid] += t;
            __syncthreads();
        }
        if (i < NN) g_csr_off[i] = sbase + sh[tid] - v;
        int tot = sh[1023];
        __syncthreads();
        if (tid == 0) sbase += tot;
        __syncthreads();
    }
    if (tid == 0) g_csr_off[NN] = sbase;
}

__global__ void k_scatter(const int* __restrict__ ei) {
    int e = blockIdx.x * blockDim.x + threadIdx.x;
    if (e < EE) {
        int src = ei[e];
        int dst = ei[EE + e];
        int pos = g_csr_off[dst] + atomicAdd(&g_cursor[dst], 1);
        g_csr_src[pos] = src;
        g_csr_eid[pos] = e;
    } else if (e < EE + NN) {
        int n = e - EE;
        int pos = g_csr_off[n + 1] - 1;  // self-loop sits in the last slot
        g_csr_src[pos] = n;
        g_csr_eid[pos] = EE + n;
    }
}

// ee[r][c] = attr_r @ W_e  (self-loop rows use segment mean of incoming attr)
__global__ void k_ee(const float* __restrict__ edge_attr, const float* __restrict__ W_e) {
    int idx = blockIdx.x * blockDim.x + threadIdx.x;
    int r = idx >> 5, c = idx & 31;
    if (r >= ET) return;
    float a0, a1, a2;
    if (r < EE) {
        a0 = edge_attr[r * 3 + 0];
        a1 = edge_attr[r * 3 + 1];
        a2 = edge_attr[r * 3 + 2];
    } else {
        int n = r - EE;
        float cnt = fmaxf(g_loop_cnt[n], 1.f);
        float inv = 1.f / cnt;
        a0 = g_loop_sum[n * 3 + 0] * inv;
        a1 = g_loop_sum[n * 3 + 1] * inv;
        a2 = g_loop_sum[n * 3 + 2] * inv;
    }
    g_ee[r * 32 + c] = a0 * W_e[c] + a1 * W_e[32 + c] + a2 * W_e[64 + c];
}

// xl = x@W_l + b_l ; xr = x@W_r + b_r  -> transposed [n][s][c] layout
// grid: (NN/8, SNAP); warp per (s, n) row
__global__ void k_xlr(const float* __restrict__ x,
                      const float* __restrict__ W_l, const float* __restrict__ b_l,
                      const float* __restrict__ W_r, const float* __restrict__ b_r) {
    __shared__ float sWl[CIN * CC];
    __shared__ float sWr[CIN * CC];
    __shared__ float sx[8][CIN];
    int tid = threadIdx.x;
    for (int i = tid; i < CIN * CC; i += 256) {
        sWl[i] = W_l[i];
        sWr[i] = W_r[i];
    }
    __syncthreads();
    int w = tid >> 5, lane = tid & 31;
    int n = blockIdx.x * 8 + w;
    int s = blockIdx.y;
    if (n >= NN) return;
    const float* xp = x + ((long)s * NN + n) * CIN;
    sx[w][lane] = xp[lane];
    sx[w][lane + 32] = xp[lane + 32];
    __syncwarp();
    float al = 0.f, ar = 0.f;
#pragma unroll
    for (int k = 0; k < CIN; k++) {
        float xv = sx[w][k];
        al += xv * sWl[k * 32 + lane];
        ar += xv * sWr[k * 32 + lane];
    }
    int o = (n * SNAP + s) * 32 + lane;
    g_xl[o] = al + b_l[lane];
    g_xr[o] = ar + b_r[lane];
}

// GATv2: warp per node, all 16 snapshots. lane = (edge-slot es, snapshot s).
// Each lane computes the full 32-channel attention dot serially (no shuffle
// reduction), exp without max-subtraction (logits are O(1) by construction,
// ratio is mathematically identical to the max-subtracted reference).
__global__ void __launch_bounds__(256, 1) k_gat(const float* __restrict__ att,
                                                const float* __restrict__ bias_gat) {
    __shared__ float s_att[32];
    __shared__ float s_bias[32];
    if (threadIdx.x < 32) {
        s_att[threadIdx.x] = att[threadIdx.x];
        s_bias[threadIdx.x] = bias_gat[threadIdx.x];
    }
    __syncthreads();

    int w = threadIdx.x >> 5, lane = threadIdx.x & 31;
    int n = blockIdx.x * 8 + w;
    if (n >= NN) return;
    int es = lane >> 4;   // edge slot 0/1
    int s  = lane & 15;   // snapshot

    // preload xr[n][s][0..31] into registers (128B per lane, dedup'd pairs)
    float xr[32];
    {
        const float4* xr4 = (const float4*)(g_xr + (n * SNAP + s) * 32);
#pragma unroll
        for (int i = 0; i < 8; i++) {
            float4 v = xr4[i];
            xr[4 * i + 0] = v.x; xr[4 * i + 1] = v.y;
            xr[4 * i + 2] = v.z; xr[4 * i + 3] = v.w;
        }
    }

    float acc[32];
#pragma unroll
    for (int c = 0; c < 32; c++) acc[c] = 0.f;
    float ssum = 0.f;

    int off = g_csr_off[n], end = g_csr_off[n + 1];
    for (int j = off; j < end; j += 2) {
        int jj = j + es;
        bool valid = jj < end;
        int jc = valid ? jj : end - 1;
        int srcj = g_csr_src[jc];
        int eid  = g_csr_eid[jc];
        const float4* xp = (const float4*)(g_xl + (srcj * SNAP + s) * 32);
        const float4* ep = (const float4*)(g_ee + eid * 32);

        float xv[32];
        float dot = 0.f;
#pragma unroll
        for (int i = 0; i < 8; i++) {
            float4 a = xp[i];
            float4 b = ep[i];
            float v0 = a.x + b.x + xr[4 * i + 0];
            float v1 = a.y + b.y + xr[4 * i + 1];
            float v2 = a.z + b.z + xr[4 * i + 2];
            float v3 = a.w + b.w + xr[4 * i + 3];
            v0 = fmaxf(v0, 0.2f * v0);   // leaky_relu(0.2), slope<1
            v1 = fmaxf(v1, 0.2f * v1);
            v2 = fmaxf(v2, 0.2f * v2);
            v3 = fmaxf(v3, 0.2f * v3);
            dot += v0 * s_att[4 * i + 0] + v1 * s_att[4 * i + 1]
                 + v2 * s_att[4 * i + 2] + v3 * s_att[4 * i + 3];
            xv[4 * i + 0] = a.x; xv[4 * i + 1] = a.y;
            xv[4 * i + 2] = a.z; xv[4 * i + 3] = a.w;
        }
        float wv = valid ? __expf(dot) : 0.f;
        ssum += wv;
#pragma unroll
        for (int c = 0; c < 32; c++) acc[c] += wv * xv[c];
    }

    // combine the two edge-slots (lanes l and l^16 hold the same snapshot)
    ssum += __shfl_xor_sync(0xffffffffu, ssum, 16);
#pragma unroll
    for (int c = 0; c < 32; c++)
        acc[c] += __shfl_xor_sync(0xffffffffu, acc[c], 16);

    if (es == 0) {
        float inv = 1.f / ssum;
        int b = s >> 3, t = s & 7;
        float4* op = (float4*)(g_gath + (((b * NN + n) * TT) + t) * 32);
#pragma unroll
        for (int i = 0; i < 8; i++) {
            float4 o;
            o.x = acc[4 * i + 0] * inv + s_bias[4 * i + 0];
            o.y = acc[4 * i + 1] * inv + s_bias[4 * i + 1];
            o.z = acc[4 * i + 2] * inv + s_bias[4 * i + 2];
            o.w = acc[4 * i + 3] * inv + s_bias[4 * i + 3];
            op[i] = o;
        }
    }
}

// GRU: warp per (b,n) sequence; lane = channel
__global__ void k_gru(const float* __restrict__ W_ih, const float* __restrict__ W_hh,
                      const float* __restrict__ b_ih, const float* __restrict__ b_hh,
                      float* __restrict__ out) {
    __shared__ float sWi[32 * 96];  // transposed: [h][g*32+c]
    __shared__ float sWh[32 * 96];
    __shared__ float sbi[96], sbh[96];
    int tid = threadIdx.x;
    for (int i = tid; i < 96 * 32; i += 256) {
        int row = i >> 5, h = i & 31;  // global layout W[row][h], row = g*32+c
        sWi[h * 96 + row] = W_ih[i];
        sWh[h * 96 + row] = W_hh[i];
    }
    for (int i = tid; i < 96; i += 256) {
        sbi[i] = b_ih[i];
        sbh[i] = b_hh[i];
    }
    __syncthreads();

    int m = blockIdx.x * 8 + (tid >> 5);
    if (m >= BB * NN) return;
    int c = tid & 31;
    int b = m / NN, n = m - b * NN;

    float bi0 = sbi[c], bi1 = sbi[32 + c], bi2 = sbi[64 + c];
    float bh0 = sbh[c], bh1 = sbh[32 + c], bh2 = sbh[64 + c];

    float h = 0.f;
    for (int t = 0; t < TT; t++) {
        float xc = g_gath[(m * TT + t) * 32 + c];
        float ir = bi0, iz = bi1, inn = bi2;
        float hr = bh0, hz = bh1, hn = bh2;
#pragma unroll
        for (int hh = 0; hh < 32; hh++) {
            float xv = __shfl_sync(0xffffffffu, xc, hh);
            float hv = __shfl_sync(0xffffffffu, h, hh);
            const float* wi = &sWi[hh * 96];
            const float* wh = &sWh[hh * 96];
            ir  += xv * wi[c];
            iz  += xv * wi[32 + c];
            inn += xv * wi[64 + c];
            hr  += hv * wh[c];
            hz  += hv * wh[32 + c];
            hn  += hv * wh[64 + c];
        }
        float r = 1.f / (1.f + __expf(-(ir + hr)));
        float z = 1.f / (1.f + __expf(-(iz + hz)));
        float pre = inn + r * hn;
        float e2 = __expf(-2.f * pre);
        float nn_ = 2.f / (1.f + e2) - 1.f;   // tanh, NaN-safe at both infinities
        h = (1.f - z) * nn_ + z * h;
        out[((long)(b * TT + t) * NN + n) * 32 + c] = h;
    }
}

// ---------------- launch ----------------
extern "C" void kernel_launch(void* const* d_in, const int* in_sizes, int n_in,
                              void* d_out, int out_size) {
    const float* x        = (const float*)d_in[0];
    const int*   ei       = (const int*)d_in[1];
    const float* eattr    = (const float*)d_in[2];
    const float* W_l      = (const float*)d_in[3];
    const float* b_l      = (const float*)d_in[4];
    const float* W_r      = (const float*)d_in[5];
    const float* b_r      = (const float*)d_in[6];
    const float* W_e      = (const float*)d_in[7];
    const float* att      = (const float*)d_in[8];
    const float* bias_gat = (const float*)d_in[9];
    const float* W_ih     = (const float*)d_in[10];
    const float* W_hh     = (const float*)d_in[11];
    const float* b_ih     = (const float*)d_in[12];
    const float* b_hh     = (const float*)d_in[13];
    float* out = (float*)d_out;

    k_zero<<<(NN + 255) / 256, 256>>>();
    k_deg<<<(EE + 255) / 256, 256>>>(ei, eattr);
    k_scan<<<1, 1024>>>();
    k_scatter<<<(EE + NN + 255) / 256, 256>>>(ei);
    k_ee<<<(ET * 32 + 255) / 256, 256>>>(eattr, W_e);
    dim3 gx((NN + 7) / 8, SNAP);
    k_xlr<<<gx, 256>>>(x, W_l, b_l, W_r, b_r);
    k_gat<<<(NN + 7) / 8, 256>>>(att, bias_gat);
    k_gru<<<(BB * NN + 7) / 8, 256>>>(W_ih, W_hh, b_ih, b_hh, out);
}

// round 3
// speedup vs baseline: 1.6160x; 1.5275x over previous
#include <cuda_runtime.h>
#include <math_constants.h>

#define NN    10000
#define EE    160000
#define ET    170000   // EE + NN self loops
#define SNAP  16       // B*T
#define TT    8
#define BB    2
#define CIN   64
#define CC    32

// ---------------- static device scratch ----------------
__device__ float g_xl[NN * SNAP * CC];       // [n][s][c]
__device__ float g_xr[NN * SNAP * CC];       // [n][s][c]
__device__ float g_ee[ET * CC];              // [edge][c]
__device__ float g_gath[BB * NN * TT * CC];  // [b][n][t][c]
__device__ float g_loop_sum[NN * 3];
__device__ float g_loop_cnt[NN];
__device__ int   g_indeg[NN];
__device__ int   g_cursor[NN];
__device__ int   g_csr_off[NN + 1];
__device__ int   g_csr_src[ET];
__device__ int   g_csr_eid[ET];

// ---------------- kernels ----------------

__global__ void k_zero() {
    int i = blockIdx.x * blockDim.x + threadIdx.x;
    if (i < NN) {
        g_loop_cnt[i] = 0.f;
        g_indeg[i] = 0;
        g_cursor[i] = 0;
        g_loop_sum[i * 3 + 0] = 0.f;
        g_loop_sum[i * 3 + 1] = 0.f;
        g_loop_sum[i * 3 + 2] = 0.f;
    }
}

__global__ void k_deg(const int* __restrict__ ei, const float* __restrict__ ea) {
    int e = blockIdx.x * blockDim.x + threadIdx.x;
    if (e >= EE) return;
    int dst = ei[EE + e];
    atomicAdd(&g_loop_sum[dst * 3 + 0], ea[e * 3 + 0]);
    atomicAdd(&g_loop_sum[dst * 3 + 1], ea[e * 3 + 1]);
    atomicAdd(&g_loop_sum[dst * 3 + 2], ea[e * 3 + 2]);
    atomicAdd(&g_loop_cnt[dst], 1.f);
    atomicAdd(&g_indeg[dst], 1);
}

// single-block scan: 1024 threads, 10 items each, one-sync shfl scan
__global__ void k_scan() {
    __shared__ int warp_sums[32];
    int tid = threadIdx.x, lane = tid & 31, wid = tid >> 5;
    int base = tid * 10;
    int v[10];
    int s = 0;
#pragma unroll
    for (int k = 0; k < 10; k++) {
        int idx = base + k;
        int val = (idx < NN) ? (g_indeg[idx] + 1) : 0;
        v[k] = s;
        s += val;
    }
    int incl = s;
#pragma unroll
    for (int o = 1; o < 32; o <<= 1) {
        int u = __shfl_up_sync(0xffffffffu, incl, o);
        if (lane >= o) incl += u;
    }
    if (lane == 31) warp_sums[wid] = incl;
    __syncthreads();
    if (tid < 32) {
        int w = warp_sums[tid];
#pragma unroll
        for (int o = 1; o < 32; o <<= 1) {
            int u = __shfl_up_sync(0xffffffffu, w, o);
            if (tid >= o) w += u;
        }
        warp_sums[tid] = w;
    }
    __syncthreads();
    int warp_off = (wid == 0) ? 0 : warp_sums[wid - 1];
    int thr_excl = warp_off + incl - s;
#pragma unroll
    for (int k = 0; k < 10; k++) {
        int idx = base + k;
        if (idx < NN) g_csr_off[idx] = thr_excl + v[k];
    }
    if (tid == 0) g_csr_off[NN] = warp_sums[31];
}

__global__ void k_scatter(const int* __restrict__ ei) {
    int e = blockIdx.x * blockDim.x + threadIdx.x;
    if (e < EE) {
        int src = ei[e];
        int dst = ei[EE + e];
        int pos = g_csr_off[dst] + atomicAdd(&g_cursor[dst], 1);
        g_csr_src[pos] = src;
        g_csr_eid[pos] = e;
    } else if (e < EE + NN) {
        int n = e - EE;
        int pos = g_csr_off[n + 1] - 1;  // self-loop in the last slot
        g_csr_src[pos] = n;
        g_csr_eid[pos] = EE + n;
    }
}

// ee[r][c] = attr_r @ W_e  (self-loop rows use segment mean of incoming attr)
__global__ void k_ee(const float* __restrict__ edge_attr, const float* __restrict__ W_e) {
    int idx = blockIdx.x * blockDim.x + threadIdx.x;
    int r = idx >> 5, c = idx & 31;
    if (r >= ET) return;
    float a0, a1, a2;
    if (r < EE) {
        a0 = edge_attr[r * 3 + 0];
        a1 = edge_attr[r * 3 + 1];
        a2 = edge_attr[r * 3 + 2];
    } else {
        int n = r - EE;
        float cnt = fmaxf(g_loop_cnt[n], 1.f);
        float inv = 1.f / cnt;
        a0 = g_loop_sum[n * 3 + 0] * inv;
        a1 = g_loop_sum[n * 3 + 1] * inv;
        a2 = g_loop_sum[n * 3 + 2] * inv;
    }
    g_ee[r * 32 + c] = a0 * W_e[c] + a1 * W_e[32 + c] + a2 * W_e[64 + c];
}

// Persistent xl/xr transform: weights loaded to smem ONCE per block
// (296 blocks), each warp processes 2 rows per iteration.
__global__ void __launch_bounds__(256) k_xlr(const float* __restrict__ x,
                      const float* __restrict__ W_l, const float* __restrict__ b_l,
                      const float* __restrict__ W_r, const float* __restrict__ b_r) {
    __shared__ float sWl[CIN * CC];
    __shared__ float sWr[CIN * CC];
    int tid = threadIdx.x;
    for (int i = tid; i < CIN * CC; i += 256) {
        sWl[i] = W_l[i];
        sWr[i] = W_r[i];
    }
    __syncthreads();
    int lane = tid & 31;
    float bl = b_l[lane], br = b_r[lane];
    int gw = blockIdx.x * 8 + (tid >> 5);
    int stride = gridDim.x * 8 * 2;
    for (int r0 = gw * 2; r0 < SNAP * NN; r0 += stride) {
        const float* xp = x + (long)r0 * CIN;
        float a_x0 = xp[lane], a_x1 = xp[lane + 32];
        float b_x0 = xp[CIN + lane], b_x1 = xp[CIN + lane + 32];
        float al_a = 0.f, ar_a = 0.f, al_b = 0.f, ar_b = 0.f;
#pragma unroll
        for (int k = 0; k < CIN; k++) {
            float xa = (k < 32) ? __shfl_sync(0xffffffffu, a_x0, k)
                                : __shfl_sync(0xffffffffu, a_x1, k - 32);
            float xb = (k < 32) ? __shfl_sync(0xffffffffu, b_x0, k)
                                : __shfl_sync(0xffffffffu, b_x1, k - 32);
            float wl = sWl[k * 32 + lane];
            float wr = sWr[k * 32 + lane];
            al_a += xa * wl; ar_a += xa * wr;
            al_b += xb * wl; ar_b += xb * wr;
        }
        int s0 = r0 / NN, n0 = r0 - s0 * NN;
        int r1 = r0 + 1;
        int s1 = r1 / NN, n1 = r1 - s1 * NN;
        g_xl[(n0 * SNAP + s0) * 32 + lane] = al_a + bl;
        g_xr[(n0 * SNAP + s0) * 32 + lane] = ar_a + br;
        g_xl[(n1 * SNAP + s1) * 32 + lane] = al_b + bl;
        g_xr[(n1 * SNAP + s1) * 32 + lane] = ar_b + br;
    }
}

// GATv2: warp per node, one edge/iteration, fully coalesced xl reads.
// Lane l handles channel-quarter q=(l&7) for snapshots s = 4k + (l>>3), k=0..3.
// Load k of the 2KB xl block (float4 #(k*32+l)) lands exactly on that (s,q).
__global__ void __launch_bounds__(256) k_gat(const float* __restrict__ att,
                                             const float* __restrict__ bias_gat) {
    int w = threadIdx.x >> 5, lane = threadIdx.x & 31;
    int n = blockIdx.x * 8 + w;
    if (n >= NN) return;
    int q = lane & 7;        // channel quarter: channels 4q..4q+3

    const float4 at4 = *(const float4*)(att + 4 * q);

    // xr preload: same coalesced pattern as xl
    float4 xr4[4];
    {
        const float4* p = (const float4*)(g_xr + n * SNAP * 32);
#pragma unroll
        for (int k = 0; k < 4; k++) xr4[k] = p[k * 32 + lane];
    }

    float4 acc[4];
#pragma unroll
    for (int k = 0; k < 4; k++) acc[k] = make_float4(0.f, 0.f, 0.f, 0.f);
    float ssum[4] = {0.f, 0.f, 0.f, 0.f};

    int off = g_csr_off[n], end = g_csr_off[n + 1];
    for (int j = off; j < end; j++) {
        int srcj = g_csr_src[j];          // broadcast
        int eid  = g_csr_eid[j];          // broadcast
        const float4* xp = (const float4*)(g_xl + srcj * SNAP * 32);
        float4 ev = *(const float4*)(g_ee + eid * 32 + 4 * q);  // broadcast/8-dedup

        float4 xv[4];
        float d[4];
#pragma unroll
        for (int k = 0; k < 4; k++) {
            float4 a = xp[k * 32 + lane];
            xv[k] = a;
            float v0 = a.x + ev.x + xr4[k].x;
            float v1 = a.y + ev.y + xr4[k].y;
            float v2 = a.z + ev.z + xr4[k].z;
            float v3 = a.w + ev.w + xr4[k].w;
            v0 = fmaxf(v0, 0.2f * v0);
            v1 = fmaxf(v1, 0.2f * v1);
            v2 = fmaxf(v2, 0.2f * v2);
            v3 = fmaxf(v3, 0.2f * v3);
            d[k] = v0 * at4.x + v1 * at4.y + v2 * at4.z + v3 * at4.w;
        }
        // reduce the 8 channel-quarters (lanes 8g..8g+7 share snapshot group g)
#pragma unroll
        for (int o = 1; o < 8; o <<= 1) {
#pragma unroll
            for (int k = 0; k < 4; k++)
                d[k] += __shfl_xor_sync(0xffffffffu, d[k], o);
        }
#pragma unroll
        for (int k = 0; k < 4; k++) {
            float wv = __expf(d[k]);
            ssum[k] += wv;
            acc[k].x += wv * xv[k].x;
            acc[k].y += wv * xv[k].y;
            acc[k].z += wv * xv[k].z;
            acc[k].w += wv * xv[k].w;
        }
    }

    const float4 bi4 = *(const float4*)(bias_gat + 4 * q);
    int g = lane >> 3;
#pragma unroll
    for (int k = 0; k < 4; k++) {
        float inv = 1.f / ssum[k];
        int s = 4 * k + g;
        int b = s >> 3, t = s & 7;
        float4 o;
        o.x = acc[k].x * inv + bi4.x;
        o.y = acc[k].y * inv + bi4.y;
        o.z = acc[k].z * inv + bi4.z;
        o.w = acc[k].w * inv + bi4.w;
        *(float4*)(g_gath + (((b * NN + n) * TT) + t) * 32 + 4 * q) = o;
    }
}

// GRU: warp per 2 sequences (shares weight LDS); lane = channel
__global__ void __launch_bounds__(256) k_gru(const float* __restrict__ W_ih,
                      const float* __restrict__ W_hh,
                      const float* __restrict__ b_ih, const float* __restrict__ b_hh,
                      float* __restrict__ out) {
    __shared__ float sWi[32 * 96];  // transposed: [h][g*32+c]
    __shared__ float sWh[32 * 96];
    __shared__ float sbi[96], sbh[96];
    int tid = threadIdx.x;
    for (int i = tid; i < 96 * 32; i += 256) {
        int row = i >> 5, h = i & 31;
        sWi[h * 96 + row] = W_ih[i];
        sWh[h * 96 + row] = W_hh[i];
    }
    for (int i = tid; i < 96; i += 256) {
        sbi[i] = b_ih[i];
        sbh[i] = b_hh[i];
    }
    __syncthreads();

    int qq = blockIdx.x * 8 + (tid >> 5);
    if (qq >= BB * NN / 2) return;
    int c = tid & 31;
    int m0 = qq * 2, m1 = qq * 2 + 1;
    int b0 = m0 / NN, n0 = m0 - b0 * NN;
    int b1 = m1 / NN, n1 = m1 - b1 * NN;

    float bi0 = sbi[c], bi1 = sbi[32 + c], bi2 = sbi[64 + c];
    float bh0 = sbh[c], bh1 = sbh[32 + c], bh2 = sbh[64 + c];

    float h0 = 0.f, h1 = 0.f;
    for (int t = 0; t < TT; t++) {
        float xc0 = g_gath[(m0 * TT + t) * 32 + c];
        float xc1 = g_gath[(m1 * TT + t) * 32 + c];
        float ir0 = bi0, iz0 = bi1, in0 = bi2, hr0 = bh0, hz0 = bh1, hn0 = bh2;
        float ir1 = bi0, iz1 = bi1, in1 = bi2, hr1 = bh0, hz1 = bh1, hn1 = bh2;
#pragma unroll
        for (int hh = 0; hh < 32; hh++) {
            float wir = sWi[hh * 96 + c];
            float wiz = sWi[hh * 96 + 32 + c];
            float win = sWi[hh * 96 + 64 + c];
            float whr = sWh[hh * 96 + c];
            float whz = sWh[hh * 96 + 32 + c];
            float whn = sWh[hh * 96 + 64 + c];
            float xv0 = __shfl_sync(0xffffffffu, xc0, hh);
            float xv1 = __shfl_sync(0xffffffffu, xc1, hh);
            float hv0 = __shfl_sync(0xffffffffu, h0, hh);
            float hv1 = __shfl_sync(0xffffffffu, h1, hh);
            ir0 += xv0 * wir; iz0 += xv0 * wiz; in0 += xv0 * win;
            hr0 += hv0 * whr; hz0 += hv0 * whz; hn0 += hv0 * whn;
            ir1 += xv1 * wir; iz1 += xv1 * wiz; in1 += xv1 * win;
            hr1 += hv1 * whr; hz1 += hv1 * whz; hn1 += hv1 * whn;
        }
        {
            float r = 1.f / (1.f + __expf(-(ir0 + hr0)));
            float z = 1.f / (1.f + __expf(-(iz0 + hz0)));
            float pre = in0 + r * hn0;
            float e2 = __expf(-2.f * pre);
            float nn_ = 2.f / (1.f + e2) - 1.f;
            h0 = (1.f - z) * nn_ + z * h0;
            out[((long)(b0 * TT + t) * NN + n0) * 32 + c] = h0;
        }
        {
            float r = 1.f / (1.f + __expf(-(ir1 + hr1)));
            float z = 1.f / (1.f + __expf(-(iz1 + hz1)));
            float pre = in1 + r * hn1;
            float e2 = __expf(-2.f * pre);
            float nn_ = 2.f / (1.f + e2) - 1.f;
            h1 = (1.f - z) * nn_ + z * h1;
            out[((long)(b1 * TT + t) * NN + n1) * 32 + c] = h1;
        }
    }
}

// ---------------- launch ----------------
extern "C" void kernel_launch(void* const* d_in, const int* in_sizes, int n_in,
                              void* d_out, int out_size) {
    const float* x        = (const float*)d_in[0];
    const int*   ei       = (const int*)d_in[1];
    const float* eattr    = (const float*)d_in[2];
    const float* W_l      = (const float*)d_in[3];
    const float* b_l      = (const float*)d_in[4];
    const float* W_r      = (const float*)d_in[5];
    const float* b_r      = (const float*)d_in[6];
    const float* W_e      = (const float*)d_in[7];
    const float* att      = (const float*)d_in[8];
    const float* bias_gat = (const float*)d_in[9];
    const float* W_ih     = (const float*)d_in[10];
    const float* W_hh     = (const float*)d_in[11];
    const float* b_ih     = (const float*)d_in[12];
    const float* b_hh     = (const float*)d_in[13];
    float* out = (float*)d_out;

    k_zero<<<(NN + 255) / 256, 256>>>();
    k_deg<<<(EE + 255) / 256, 256>>>(ei, eattr);
    k_scan<<<1, 1024>>>();
    k_scatter<<<(EE + NN + 255) / 256, 256>>>(ei);
    k_ee<<<(ET * 32 + 255) / 256, 256>>>(eattr, W_e);
    k_xlr<<<296, 256>>>(x, W_l, b_l, W_r, b_r);
    k_gat<<<(NN + 7) / 8, 256>>>(att, bias_gat);
    k_gru<<<(BB * NN / 2 + 7) / 8, 256>>>(W_ih, W_hh, b_ih, b_hh, out);
}

// round 4
// speedup vs baseline: 1.9015x; 1.1766x over previous
#include <cuda_runtime.h>
#include <math_constants.h>

#define NN    10000
#define EE    160000
#define ET    170000   // EE + NN self loops
#define SNAP  16       // B*T
#define TT    8
#define BB    2
#define CIN   64
#define CC    32

// ---------------- static device scratch ----------------
__device__ float g_xl[NN * SNAP * CC];       // [n][s][c]
__device__ float g_xr[NN * SNAP * CC];       // [n][s][c]
__device__ float g_ee[ET * CC];              // [edge][c]
__device__ float g_loop_sum[NN * 3];
__device__ float g_loop_cnt[NN];
__device__ int   g_indeg[NN];
__device__ int   g_cursor[NN];
__device__ int   g_csr_off[NN + 1];
__device__ int   g_csr_src[ET];
__device__ int   g_csr_eid[ET];

// ---------------- prep kernels ----------------

__global__ void k_zero() {
    int i = blockIdx.x * blockDim.x + threadIdx.x;
    if (i < NN) {
        g_loop_cnt[i] = 0.f;
        g_indeg[i] = 0;
        g_cursor[i] = 0;
        g_loop_sum[i * 3 + 0] = 0.f;
        g_loop_sum[i * 3 + 1] = 0.f;
        g_loop_sum[i * 3 + 2] = 0.f;
    }
}

__global__ void k_deg(const int* __restrict__ ei, const float* __restrict__ ea) {
    int e = blockIdx.x * blockDim.x + threadIdx.x;
    if (e >= EE) return;
    int dst = ei[EE + e];
    atomicAdd(&g_loop_sum[dst * 3 + 0], ea[e * 3 + 0]);
    atomicAdd(&g_loop_sum[dst * 3 + 1], ea[e * 3 + 1]);
    atomicAdd(&g_loop_sum[dst * 3 + 2], ea[e * 3 + 2]);
    atomicAdd(&g_loop_cnt[dst], 1.f);
    atomicAdd(&g_indeg[dst], 1);
}

// single-block scan: 1024 threads, 10 items each, one-sync shfl scan
__global__ void k_scan() {
    __shared__ int warp_sums[32];
    int tid = threadIdx.x, lane = tid & 31, wid = tid >> 5;
    int base = tid * 10;
    int v[10];
    int s = 0;
#pragma unroll
    for (int k = 0; k < 10; k++) {
        int idx = base + k;
        int val = (idx < NN) ? (g_indeg[idx] + 1) : 0;
        v[k] = s;
        s += val;
    }
    int incl = s;
#pragma unroll
    for (int o = 1; o < 32; o <<= 1) {
        int u = __shfl_up_sync(0xffffffffu, incl, o);
        if (lane >= o) incl += u;
    }
    if (lane == 31) warp_sums[wid] = incl;
    __syncthreads();
    if (tid < 32) {
        int w = warp_sums[tid];
#pragma unroll
        for (int o = 1; o < 32; o <<= 1) {
            int u = __shfl_up_sync(0xffffffffu, w, o);
            if (tid >= o) w += u;
        }
        warp_sums[tid] = w;
    }
    __syncthreads();
    int warp_off = (wid == 0) ? 0 : warp_sums[wid - 1];
    int thr_excl = warp_off + incl - s;
#pragma unroll
    for (int k = 0; k < 10; k++) {
        int idx = base + k;
        if (idx < NN) g_csr_off[idx] = thr_excl + v[k];
    }
    if (tid == 0) g_csr_off[NN] = warp_sums[31];
}

__global__ void k_scatter(const int* __restrict__ ei) {
    int e = blockIdx.x * blockDim.x + threadIdx.x;
    if (e < EE) {
        int src = ei[e];
        int dst = ei[EE + e];
        int pos = g_csr_off[dst] + atomicAdd(&g_cursor[dst], 1);
        g_csr_src[pos] = src;
        g_csr_eid[pos] = e;
    } else if (e < EE + NN) {
        int n = e - EE;
        int pos = g_csr_off[n + 1] - 1;  // self-loop in the last slot
        g_csr_src[pos] = n;
        g_csr_eid[pos] = EE + n;
    }
}

// ee[r][c] = attr_r @ W_e (self-loop rows: segment mean of incoming attr)
__global__ void k_ee(const float* __restrict__ edge_attr, const float* __restrict__ W_e) {
    int idx = blockIdx.x * blockDim.x + threadIdx.x;
    int r = idx >> 5, c = idx & 31;
    if (r >= ET) return;
    float a0, a1, a2;
    if (r < EE) {
        a0 = edge_attr[r * 3 + 0];
        a1 = edge_attr[r * 3 + 1];
        a2 = edge_attr[r * 3 + 2];
    } else {
        int n = r - EE;
        float cnt = fmaxf(g_loop_cnt[n], 1.f);
        float inv = 1.f / cnt;
        a0 = g_loop_sum[n * 3 + 0] * inv;
        a1 = g_loop_sum[n * 3 + 1] * inv;
        a2 = g_loop_sum[n * 3 + 2] * inv;
    }
    g_ee[r * 32 + c] = a0 * W_e[c] + a1 * W_e[32 + c] + a2 * W_e[64 + c];
}

// Persistent xl/xr transform; packed {Wl,Wr} float2 smem; 2 rows/warp/iter.
__global__ void __launch_bounds__(256) k_xlr(const float* __restrict__ x,
                      const float* __restrict__ W_l, const float* __restrict__ b_l,
                      const float* __restrict__ W_r, const float* __restrict__ b_r) {
    __shared__ float2 sW[CIN * CC];
    int tid = threadIdx.x;
    for (int i = tid; i < CIN * CC; i += 256)
        sW[i] = make_float2(W_l[i], W_r[i]);
    __syncthreads();
    int lane = tid & 31;
    float bl = b_l[lane], br = b_r[lane];
    int gw = blockIdx.x * 8 + (tid >> 5);
    int stride = gridDim.x * 8 * 2;
    for (int r0 = gw * 2; r0 < SNAP * NN; r0 += stride) {
        const float* xp = x + (long)r0 * CIN;
        float a_x0 = xp[lane], a_x1 = xp[lane + 32];
        float b_x0 = xp[CIN + lane], b_x1 = xp[CIN + lane + 32];
        float al_a = 0.f, ar_a = 0.f, al_b = 0.f, ar_b = 0.f;
#pragma unroll
        for (int k = 0; k < CIN; k++) {
            float xa = (k < 32) ? __shfl_sync(0xffffffffu, a_x0, k)
                                : __shfl_sync(0xffffffffu, a_x1, k - 32);
            float xb = (k < 32) ? __shfl_sync(0xffffffffu, b_x0, k)
                                : __shfl_sync(0xffffffffu, b_x1, k - 32);
            float2 w = sW[k * 32 + lane];
            al_a += xa * w.x; ar_a += xa * w.y;
            al_b += xb * w.x; ar_b += xb * w.y;
        }
        int s0 = r0 / NN, n0 = r0 - s0 * NN;
        int r1 = r0 + 1;
        int s1 = r1 / NN, n1 = r1 - s1 * NN;
        g_xl[(n0 * SNAP + s0) * 32 + lane] = al_a + bl;
        g_xr[(n0 * SNAP + s0) * 32 + lane] = ar_a + br;
        g_xl[(n1 * SNAP + s1) * 32 + lane] = al_b + bl;
        g_xr[(n1 * SNAP + s1) * 32 + lane] = ar_b + br;
    }
}

// Fused GATv2 + GRU: warp per node (grid exactly NN/8 nodes, no remainder).
// GAT phase: lane l = (snapshot-group g=l>>3, channel-quarter q=l&7), fully
// coalesced xl gathers, software-pipelined edge loop (prefetch next edge).
// GRU phase: per-warp smem transpose -> lane = channel, 2 sequences/warp.
__global__ void __launch_bounds__(256) k_gatgru(
        const float* __restrict__ att, const float* __restrict__ bias_gat,
        const float* __restrict__ W_ih, const float* __restrict__ W_hh,
        const float* __restrict__ b_ih, const float* __restrict__ b_hh,
        float* __restrict__ out) {
    __shared__ float2 sW[3][32][32];   // [gate][h][c] = {W_ih, W_hh}
    __shared__ float  sb[6][32];       // bi_r,bi_z,bi_n,bh_r,bh_z,bh_n
    __shared__ float  s_tr[8][16][32]; // per-warp transpose [warp][s][c]

    int tid = threadIdx.x;
    for (int i = tid; i < 3 * 32 * 32; i += 256) {
        int row = i >> 5, h = i & 31;       // row = g*32+c
        int g = row >> 5, c = row & 31;
        sW[g][h][c] = make_float2(W_ih[i], W_hh[i]);
    }
    if (tid < 96) {
        int g = tid >> 5, c = tid & 31;
        sb[g][c] = b_ih[tid];
        sb[3 + g][c] = b_hh[tid];
    }
    __syncthreads();

    int w = tid >> 5, lane = tid & 31;
    int n = blockIdx.x * 8 + w;            // always < NN (grid = NN/8 exact)
    int q = lane & 7, g = lane >> 3;

    const float4 at4 = *(const float4*)(att + 4 * q);

    float4 xr4[4];
    {
        const float4* p = (const float4*)(g_xr + n * SNAP * 32);
#pragma unroll
        for (int k = 0; k < 4; k++) xr4[k] = p[k * 32 + lane];
    }

    float4 acc[4];
#pragma unroll
    for (int k = 0; k < 4; k++) acc[k] = make_float4(0.f, 0.f, 0.f, 0.f);
    float ssum[4] = {0.f, 0.f, 0.f, 0.f};

    int off = g_csr_off[n], end = g_csr_off[n + 1];  // end > off (self-loop)

    // prime the pipeline
    float4 a[4], ev;
    {
        int src = g_csr_src[off], eid = g_csr_eid[off];
        const float4* xp = (const float4*)(g_xl + src * SNAP * 32);
        ev = *(const float4*)(g_ee + eid * 32 + 4 * q);
#pragma unroll
        for (int k = 0; k < 4; k++) a[k] = xp[k * 32 + lane];
    }

    for (int j = off; j < end; j++) {
        // prefetch next edge (clamped; warp-uniform)
        int jn = (j + 1 < end) ? j + 1 : j;
        int src_n = g_csr_src[jn], eid_n = g_csr_eid[jn];
        const float4* xpn = (const float4*)(g_xl + src_n * SNAP * 32);
        float4 evn = *(const float4*)(g_ee + eid_n * 32 + 4 * q);
        float4 an[4];
#pragma unroll
        for (int k = 0; k < 4; k++) an[k] = xpn[k * 32 + lane];

        // compute on current edge
        float d[4];
#pragma unroll
        for (int k = 0; k < 4; k++) {
            float v0 = a[k].x + ev.x + xr4[k].x;
            float v1 = a[k].y + ev.y + xr4[k].y;
            float v2 = a[k].z + ev.z + xr4[k].z;
            float v3 = a[k].w + ev.w + xr4[k].w;
            v0 = fmaxf(v0, 0.2f * v0);
            v1 = fmaxf(v1, 0.2f * v1);
            v2 = fmaxf(v2, 0.2f * v2);
            v3 = fmaxf(v3, 0.2f * v3);
            d[k] = v0 * at4.x + v1 * at4.y + v2 * at4.z + v3 * at4.w;
        }
#pragma unroll
        for (int o = 1; o < 8; o <<= 1) {
#pragma unroll
            for (int k = 0; k < 4; k++)
                d[k] += __shfl_xor_sync(0xffffffffu, d[k], o);
        }
#pragma unroll
        for (int k = 0; k < 4; k++) {
            float wv = __expf(d[k]);
            ssum[k] += wv;
            acc[k].x += wv * a[k].x;
            acc[k].y += wv * a[k].y;
            acc[k].z += wv * a[k].z;
            acc[k].w += wv * a[k].w;
        }
#pragma unroll
        for (int k = 0; k < 4; k++) a[k] = an[k];
        ev = evn;
    }

    // write GAT result (with bias + normalize) into per-warp transpose buffer
    const float4 bi4 = *(const float4*)(bias_gat + 4 * q);
#pragma unroll
    for (int k = 0; k < 4; k++) {
        float inv = 1.f / ssum[k];
        int s = 4 * k + g;
        float* tp = &s_tr[w][s][4 * q];
        tp[0] = acc[k].x * inv + bi4.x;
        tp[1] = acc[k].y * inv + bi4.y;
        tp[2] = acc[k].z * inv + bi4.z;
        tp[3] = acc[k].w * inv + bi4.w;
    }
    __syncwarp();

    // ---- GRU phase: lane = channel c; 2 sequences (b=0 -> s=t, b=1 -> s=8+t)
    int c = lane;
    float bi0 = sb[0][c], bi1 = sb[1][c], bi2 = sb[2][c];
    float bh0 = sb[3][c], bh1 = sb[4][c], bh2 = sb[5][c];

    float h0 = 0.f, h1 = 0.f;
    for (int t = 0; t < TT; t++) {
        float ir0 = bi0, iz0 = bi1, in0 = bi2, hr0 = bh0, hz0 = bh1, hn0 = bh2;
        float ir1 = bi0, iz1 = bi1, in1 = bi2, hr1 = bh0, hz1 = bh1, hn1 = bh2;
#pragma unroll
        for (int hh = 0; hh < 32; hh++) {
            float xv0 = s_tr[w][t][hh];        // LDS broadcast
            float xv1 = s_tr[w][8 + t][hh];
            float hv0 = __shfl_sync(0xffffffffu, h0, hh);
            float hv1 = __shfl_sync(0xffffffffu, h1, hh);
            float2 wr_ = sW[0][hh][c];
            float2 wz_ = sW[1][hh][c];
            float2 wn_ = sW[2][hh][c];
            ir0 += xv0 * wr_.x; hr0 += hv0 * wr_.y;
            iz0 += xv0 * wz_.x; hz0 += hv0 * wz_.y;
            in0 += xv0 * wn_.x; hn0 += hv0 * wn_.y;
            ir1 += xv1 * wr_.x; hr1 += hv1 * wr_.y;
            iz1 += xv1 * wz_.x; hz1 += hv1 * wz_.y;
            in1 += xv1 * wn_.x; hn1 += hv1 * wn_.y;
        }
        {
            float r = 1.f / (1.f + __expf(-(ir0 + hr0)));
            float z = 1.f / (1.f + __expf(-(iz0 + hz0)));
            float pre = in0 + r * hn0;
            float e2 = __expf(-2.f * pre);
            float nn_ = 2.f / (1.f + e2) - 1.f;
            h0 = (1.f - z) * nn_ + z * h0;
            out[((long)t * NN + n) * 32 + c] = h0;
        }
        {
            float r = 1.f / (1.f + __expf(-(ir1 + hr1)));
            float z = 1.f / (1.f + __expf(-(iz1 + hz1)));
            float pre = in1 + r * hn1;
            float e2 = __expf(-2.f * pre);
            float nn_ = 2.f / (1.f + e2) - 1.f;
            h1 = (1.f - z) * nn_ + z * h1;
            out[((long)(TT + t) * NN + n) * 32 + c] = h1;
        }
    }
}

// ---------------- launch ----------------
extern "C" void kernel_launch(void* const* d_in, const int* in_sizes, int n_in,
                              void* d_out, int out_size) {
    const float* x        = (const float*)d_in[0];
    const int*   ei       = (const int*)d_in[1];
    const float* eattr    = (const float*)d_in[2];
    const float* W_l      = (const float*)d_in[3];
    const float* b_l      = (const float*)d_in[4];
    const float* W_r      = (const float*)d_in[5];
    const float* b_r      = (const float*)d_in[6];
    const float* W_e      = (const float*)d_in[7];
    const float* att      = (const float*)d_in[8];
    const float* bias_gat = (const float*)d_in[9];
    const float* W_ih     = (const float*)d_in[10];
    const float* W_hh     = (const float*)d_in[11];
    const float* b_ih     = (const float*)d_in[12];
    const float* b_hh     = (const float*)d_in[13];
    float* out = (float*)d_out;

    k_zero<<<(NN + 255) / 256, 256>>>();
    k_deg<<<(EE + 255) / 256, 256>>>(ei, eattr);
    k_scan<<<1, 1024>>>();
    k_scatter<<<(EE + NN + 255) / 256, 256>>>(ei);
    k_ee<<<(ET * 32 + 255) / 256, 256>>>(eattr, W_e);
    k_xlr<<<296, 256>>>(x, W_l, b_l, W_r, b_r);
    k_gatgru<<<NN / 8, 256>>>(att, bias_gat, W_ih, W_hh, b_ih, b_hh, out);
}